// round 13
// baseline (speedup 1.0000x reference)
#include <cuda_runtime.h>
#include <cuda_fp16.h>

#define D      128
#define D4     32
#define DH2    32
#define KHOPS  10
#define BM     32
#define NTHR   256

static const int NMAX = 50000;
static const int EMAX = 625000;
static const int GBMAX = 512;

// ---------------- scratch (device globals; no allocation allowed) ----------
__device__ __half g_bufA[NMAX * D];     // h ping (fp16 state)
__device__ __half g_bufB[NMAX * D];     // h pong
__device__ int    g_deg[NMAX];
__device__ int    g_rowptr[NMAX + 1];
__device__ int    g_cursor[NMAX];
__device__ float  g_dinv[NMAX];
__device__ int2   g_csr[EMAX];          // {src, bitcast(dinv[src])}
__device__ __half g_Wh[D * D];          // W in fp16, [o][k]
__device__ float  g_coeff[KHOPS + 1];
__device__ int    g_is64;
__device__ int    g_bsum[GBMAX];
__device__ unsigned          g_bar_count;
__device__ volatile unsigned g_bar_gen;

// ---------------- software grid barrier -------------------------------------
__device__ __forceinline__ void gridbar() {
    __syncthreads();
    if (threadIdx.x == 0) {
        __threadfence();
        unsigned gen = g_bar_gen;
        if (atomicAdd(&g_bar_count, 1u) == gridDim.x - 1) {
            g_bar_count = 0;
            __threadfence();
            g_bar_gen = gen + 1;
        } else {
            while (g_bar_gen == gen) __nanosleep(64);
        }
        __threadfence();
    }
    __syncthreads();
}

// ---------------- block exclusive scan (256 thr); ws = 16 ints shared ------
__device__ __forceinline__ int blk_excl_scan(int v, int* ws) {
    int lane = threadIdx.x & 31, wid = threadIdx.x >> 5;
    int inc = v;
#pragma unroll
    for (int off = 1; off < 32; off <<= 1) {
        int t = __shfl_up_sync(0xffffffffu, inc, off);
        if (lane >= off) inc += t;
    }
    if (lane == 31) ws[wid] = inc;
    __syncthreads();
    if (wid == 0 && lane < 8) {
        int wv = ws[lane];
#pragma unroll
        for (int off = 1; off < 8; off <<= 1) {
            int t = __shfl_up_sync(0xffu, wv, off, 8);
            if (lane >= off) wv += t;
        }
        ws[lane] = wv;
        if (lane == 7) ws[15] = wv;
    }
    __syncthreads();
    return inc - v + (wid ? ws[wid - 1] : 0);
}

__device__ __forceinline__ int load_idx(const void* ei, long long pos) {
    if (g_is64) return (int)((const long long*)ei)[pos];
    return ((const int*)ei)[pos];
}

// ------------- fp16 helpers --------------------------------------------------
__device__ __forceinline__ void fma_h4(uint2 p, float w, float4& a) {
    float2 lo = __half22float2(*(const __half2*)&p.x);
    float2 hi = __half22float2(*(const __half2*)&p.y);
    a.x = fmaf(w, lo.x, a.x); a.y = fmaf(w, lo.y, a.y);
    a.z = fmaf(w, hi.x, a.z); a.w = fmaf(w, hi.y, a.w);
}
__device__ __forceinline__ uint2 pack_h4(float4 r) {
    __half2 lo = __floats2half2_rn(r.x, r.y);
    __half2 hi = __floats2half2_rn(r.z, r.w);
    uint2 p;
    p.x = *(const unsigned int*)&lo;
    p.y = *(const unsigned int*)&hi;
    return p;
}
__device__ __forceinline__ unsigned int smem_u32(const void* p) {
    return (unsigned int)__cvta_generic_to_shared(p);
}

// ================= LAUNCH 1: persistent preprocessing (small grid) ==========
__global__ void __launch_bounds__(NTHR) k_prep(
    const void* __restrict__ ei, const float* __restrict__ tptr,
    const float* __restrict__ W, int N, int E)
{
    __shared__ int ws[16];
    int tid  = threadIdx.x;
    int bid  = blockIdx.x;
    int lane = tid & 31;
    int warp = tid >> 5;
    int gtid = bid * NTHR + tid;
    int nthr = gridDim.x * NTHR;

    for (int i = gtid; i < N; i += nthr) g_deg[i] = 0;
    for (int i = gtid; i < D * D; i += nthr) g_Wh[i] = __float2half(W[i]);
    if (gtid == 0) {
        const int* a = (const int*)ei;
        int is64 = 1;
#pragma unroll
        for (int j = 1; j < 32; j += 2)
            if (a[j] != 0) is64 = 0;
        g_is64 = is64;
        float t = *tptr;
        float cc = expf(-t);
        g_coeff[0] = cc;
        for (int k = 1; k <= KHOPS; ++k) { cc = cc * t / (float)k; g_coeff[k] = cc; }
    }
    gridbar();

    for (int e = gtid; e < E; e += nthr) {
        int dst = load_idx(ei, (long long)E + e);
        atomicAdd(&g_deg[dst], 1);
    }
    gridbar();

    int chunk  = (N + gridDim.x - 1) / gridDim.x;
    int rounds = (chunk + NTHR - 1) / NTHR;
    int base   = bid * chunk;
    {
        int sum = 0;
        for (int r = 0; r < rounds; ++r) {
            int i = base + r * NTHR + tid;
            int v = (i < base + chunk && i < N) ? g_deg[i] : 0;
#pragma unroll
            for (int off = 16; off > 0; off >>= 1)
                v += __shfl_down_sync(0xffffffffu, v, off);
            if (lane == 0) sum += v;
        }
        if (lane == 0) ws[warp] = sum;
        __syncthreads();
        if (warp == 0 && lane < 8) {
            int s = ws[lane];
#pragma unroll
            for (int off = 4; off > 0; off >>= 1)
                s += __shfl_down_sync(0xffu, s, off, 8);
            if (lane == 0) g_bsum[bid] = s;
        }
        __syncthreads();
    }
    gridbar();

    if (bid == 0) {
        int nb = gridDim.x;
        int carry = 0;
        for (int r = 0; r * NTHR < nb; ++r) {
            int i = r * NTHR + tid;
            int v = (i < nb) ? g_bsum[i] : 0;
            int ex = blk_excl_scan(v, ws);
            int tot = ws[15];
            __syncthreads();
            if (i < nb) g_bsum[i] = ex + carry;
            carry += tot;
        }
    }
    gridbar();

    {
        int carry = g_bsum[bid];
        for (int r = 0; r < rounds; ++r) {
            int i = base + r * NTHR + tid;
            int inb = (i < base + chunk && i < N);
            int d = inb ? g_deg[i] : 0;
            int ex = blk_excl_scan(d, ws);
            int tot = ws[15];
            __syncthreads();
            if (inb) {
                int excl = ex + carry;
                g_rowptr[i] = excl;
                g_cursor[i] = excl;
                g_dinv[i]   = rsqrtf((float)d + 1.0f);
                if (i == N - 1) g_rowptr[N] = excl + d;
            }
            carry += tot;
        }
    }
    gridbar();

    for (int e = gtid; e < E; e += nthr) {
        int src = load_idx(ei, e);
        int dst = load_idx(ei, (long long)E + e);
        int pos = atomicAdd(&g_cursor[dst], 1);
        g_csr[pos] = make_int2(src, __float_as_int(g_dinv[src]));
    }
}

// ================= LAUNCH 2: HMMA GEMM (known good) =========================
__global__ void __launch_bounds__(256) k_gemm_mma(
    const float* __restrict__ x, const float* __restrict__ b,
    float* __restrict__ out, int n)
{
    __shared__ __align__(16) __half sA[BM][D + 8];
    __shared__ __align__(16) __half sW[D][D + 8];

    int tid  = threadIdx.x;
    int warp = tid >> 5;
    int lane = tid & 31;
    int rowb = blockIdx.x * BM;
    int rows = n - rowb; if (rows > BM) rows = BM;

    const uint4* Wh4 = (const uint4*)g_Wh;
#pragma unroll
    for (int i = tid; i < D * (D / 8); i += 256) {
        int r = i >> 4, c = i & 15;
        *(uint4*)&sW[r][c * 8] = __ldg(&Wh4[r * 16 + c]);
    }
    const float4* x4 = (const float4*)(x + (long long)rowb * D);
    for (int i = tid; i < rows * D4; i += 256) {
        int r = i >> 5, c = i & 31;
        float4 v = x4[i];
        *(half2*)&sA[r][c * 4]     = __floats2half2_rn(v.x, v.y);
        *(half2*)&sA[r][c * 4 + 2] = __floats2half2_rn(v.z, v.w);
    }
    __syncthreads();

    int rg = warp & 1, cg = warp >> 1;
    int r0 = rg * 16;

    float acc[4][4];
#pragma unroll
    for (int j = 0; j < 4; ++j)
#pragma unroll
        for (int q = 0; q < 4; ++q) acc[j][q] = 0.f;

    int aRow = r0 + (lane & 15);
    int aCol = (lane >> 4) << 3;
    int bN = (lane & 7) + ((lane >> 4) << 3);
    int bK = ((lane >> 3) & 1) << 3;

#pragma unroll
    for (int k0 = 0; k0 < D; k0 += 16) {
        unsigned int a0, a1, a2, a3;
        unsigned int aAddr = smem_u32(&sA[aRow][k0 + aCol]);
        asm volatile("ldmatrix.sync.aligned.m8n8.x4.shared.b16 {%0,%1,%2,%3}, [%4];"
                     : "=r"(a0), "=r"(a1), "=r"(a2), "=r"(a3) : "r"(aAddr));
#pragma unroll
        for (int h16 = 0; h16 < 2; ++h16) {
            int nbase = cg * 32 + h16 * 16;
            unsigned int b0, b1, b2, b3;
            unsigned int bAddr = smem_u32(&sW[nbase + bN][k0 + bK]);
            asm volatile("ldmatrix.sync.aligned.m8n8.x4.shared.b16 {%0,%1,%2,%3}, [%4];"
                         : "=r"(b0), "=r"(b1), "=r"(b2), "=r"(b3) : "r"(bAddr));
            int j0 = h16 * 2;
            asm volatile("mma.sync.aligned.m16n8k16.row.col.f32.f16.f16.f32 "
                         "{%0,%1,%2,%3},{%4,%5,%6,%7},{%8,%9},{%0,%1,%2,%3};"
                         : "+f"(acc[j0][0]), "+f"(acc[j0][1]), "+f"(acc[j0][2]), "+f"(acc[j0][3])
                         : "r"(a0), "r"(a1), "r"(a2), "r"(a3), "r"(b0), "r"(b1));
            asm volatile("mma.sync.aligned.m16n8k16.row.col.f32.f16.f16.f32 "
                         "{%0,%1,%2,%3},{%4,%5,%6,%7},{%8,%9},{%0,%1,%2,%3};"
                         : "+f"(acc[j0+1][0]), "+f"(acc[j0+1][1]), "+f"(acc[j0+1][2]), "+f"(acc[j0+1][3])
                         : "r"(a0), "r"(a1), "r"(a2), "r"(a3), "r"(b2), "r"(b3));
        }
    }

    float c0 = g_coeff[0];
    int mlo = rowb + r0 + (lane >> 2);
    int mhi = mlo + 8;
    __half2* h0 = (__half2*)g_bufA;

#pragma unroll
    for (int j = 0; j < 4; ++j) {
        int col = cg * 32 + j * 8 + ((lane & 3) << 1);
        float2 bb = __ldg((const float2*)(b + col));
        if (mlo < n) {
            long long idx = (long long)mlo * D + col;
            *(float2*)(out + idx) = make_float2(fmaf(c0, acc[j][0], bb.x),
                                                fmaf(c0, acc[j][1], bb.y));
            h0[idx >> 1] = __floats2half2_rn(acc[j][0], acc[j][1]);
        }
        if (mhi < n) {
            long long idx = (long long)mhi * D + col;
            *(float2*)(out + idx) = make_float2(fmaf(c0, acc[j][2], bb.x),
                                                fmaf(c0, acc[j][3], bb.y));
            h0[idx >> 1] = __floats2half2_rn(acc[j][2], acc[j][3]);
        }
    }
}

// ================= LAUNCH 3..12: one hop, cooperative-CSR version ===========
// Warp per node. The warp's csr slice is CONTIGUOUS: all 32 lanes fetch one
// int2 each in a single coalesced load, then src/w are distributed by shfl.
// Gathers issue back-to-back with no memory dependency between batches.
// Lanes beyond deg hold (src=0, w=0): dummy gathers of row 0 are L1-hot and
// contribute 0 — branch-free partial batches.
__global__ void __launch_bounds__(256) k_hop(
    int flip, int k, int n, float4* __restrict__ out, int do_out, int write_h)
{
    int gw = (blockIdx.x * blockDim.x + threadIdx.x) >> 5;
    if (gw >= n) return;
    int lane = threadIdx.x & 31;

    const uint2* __restrict__ hin  = flip ? (const uint2*)g_bufB : (const uint2*)g_bufA;
    uint2*       __restrict__ hout = flip ? (uint2*)g_bufA       : (uint2*)g_bufB;

    int beg = __ldg(&g_rowptr[gw]);
    int end = __ldg(&g_rowptr[gw + 1]);
    int deg = end - beg;

    uint2 ps = __ldg(&hin[gw * DH2 + lane]);   // self row

    // cooperative csr fetch: one coalesced LDG covers up to 32 edges
    int cpos = beg + lane;
    int2 myc = (cpos < end) ? __ldg(&g_csr[cpos]) : make_int2(0, 0);

    float4 acc  = make_float4(0.f,0.f,0.f,0.f);
    float4 acc2 = make_float4(0.f,0.f,0.f,0.f);

    int processed = 0;
    while (processed < deg) {
        int rem = deg - processed; if (rem > 32) rem = 32;
        int nbatch = (rem + 7) >> 3;
        for (int bth = 0; bth < nbatch; ++bth) {
            int off = bth * 8;
            uint2 p[8];
#pragma unroll
            for (int i = 0; i < 8; ++i) {
                int s = __shfl_sync(0xffffffffu, myc.x, off + i);
                p[i] = __ldg(&hin[s * DH2 + lane]);
            }
#pragma unroll
            for (int i = 0; i < 8; ++i) {
                float w = __int_as_float(__shfl_sync(0xffffffffu, myc.y, off + i));
                fma_h4(p[i], w, (i & 1) ? acc2 : acc);
            }
        }
        processed += 32;
        if (processed < deg) {
            int np = beg + processed + lane;
            myc = (np < end) ? __ldg(&g_csr[np]) : make_int2(0, 0);
        }
    }

    float di  = __ldg(&g_dinv[gw]);
    float di2 = di * di;
    float2 slo = __half22float2(*(const __half2*)&ps.x);
    float2 shi = __half22float2(*(const __half2*)&ps.y);

    float4 r;
    r.x = fmaf(di, acc.x + acc2.x, di2 * slo.x);
    r.y = fmaf(di, acc.y + acc2.y, di2 * slo.y);
    r.z = fmaf(di, acc.z + acc2.z, di2 * shi.x);
    r.w = fmaf(di, acc.w + acc2.w, di2 * shi.y);

    int idx = gw * DH2 + lane;
    if (write_h) hout[idx] = pack_h4(r);

    if (do_out) {
        float cp = g_coeff[k - 1];
        float c  = g_coeff[k];
        float4 o = out[idx];
        o.x = fmaf(cp, slo.x, o.x);
        o.y = fmaf(cp, slo.y, o.y);
        o.z = fmaf(cp, shi.x, o.z);
        o.w = fmaf(cp, shi.y, o.w);
        o.x = fmaf(c, r.x, o.x);
        o.y = fmaf(c, r.y, o.y);
        o.z = fmaf(c, r.z, o.z);
        o.w = fmaf(c, r.w, o.w);
        out[idx] = o;
    }
}

// ---------------- launch ------------------------------------------------------
extern "C" void kernel_launch(void* const* d_in, const int* in_sizes, int n_in,
                              void* d_out, int out_size) {
    const float* x  = (const float*)d_in[0];
    const void*  ei = d_in[1];
    const float* t  = (const float*)d_in[2];
    const float* W  = (const float*)d_in[3];
    const float* b  = (const float*)d_in[4];
    float* out = (float*)d_out;

    int N = in_sizes[0] / D;
    int E = in_sizes[1] / 2;

    int dev = 0;
    cudaGetDevice(&dev);
    int nsm = 148;
    cudaDeviceGetAttribute(&nsm, cudaDevAttrMultiProcessorCount, dev);

    int nb_prep = nsm * 2;
    if (nb_prep > GBMAX) nb_prep = GBMAX;

    k_prep<<<nb_prep, NTHR>>>(ei, t, W, N, E);
    k_gemm_mma<<<(N + BM - 1) / BM, 256>>>(x, b, out, N);

    int hop_blocks = (N + 7) / 8;
    for (int k = 1; k <= KHOPS; ++k) {
        int flip    = (k - 1) & 1;
        int do_out  = (k & 1) == 0;
        int write_h = (k < KHOPS);
        k_hop<<<hop_blocks, 256>>>(flip, k, N, (float4*)out, do_out, write_h);
    }
}

// round 14
// speedup vs baseline: 1.5119x; 1.5119x over previous
#include <cuda_runtime.h>
#include <cuda_fp16.h>

#define D      128
#define D4     32
#define DH2    32
#define KHOPS  10
#define SCAN_T 1024
#define BM     32

static const int NMAX = 50000;
static const int EMAX = 625000;
static const int BMAX = 64;

// ---------------- scratch (device globals; no allocation allowed) ----------
__device__ __half g_bufA[NMAX * D];     // h ping (fp16 state)
__device__ __half g_bufB[NMAX * D];     // h pong
__device__ int    g_deg[NMAX];
__device__ int    g_rowptr[NMAX + 1];
__device__ int    g_cursor[NMAX];
__device__ float  g_dinv[NMAX];
__device__ int2   g_csr[EMAX];          // {src, bitcast(dinv[src])}
__device__ __half g_Wh[D * D];          // W in fp16, [o][k]
__device__ float  g_coeff[KHOPS + 1];
__device__ int    g_is64;
__device__ int    g_bsum[BMAX];

// ---------------- fused setup: W->fp16 + deg zero + detect + coeffs --------
__global__ void k_setup(const void* __restrict__ ei,
                        const float* __restrict__ t_ptr,
                        const float* __restrict__ W, int n) {
    int i = blockIdx.x * blockDim.x + threadIdx.x;
    if (i < D * D) g_Wh[i] = __float2half(W[i]);
    if (i < n)     g_deg[i] = 0;
    if (i == 0) {
        const int* a = (const int*)ei;
        int is64 = 1;
#pragma unroll
        for (int j = 1; j < 32; j += 2)
            if (a[j] != 0) is64 = 0;
        g_is64 = is64;
        float t = *t_ptr;
        float cc = expf(-t);
        g_coeff[0] = cc;
        for (int k = 1; k <= KHOPS; ++k) { cc = cc * t / (float)k; g_coeff[k] = cc; }
    }
}

__device__ __forceinline__ int load_idx(const void* ei, long long pos) {
    if (g_is64) return (int)((const long long*)ei)[pos];
    return ((const int*)ei)[pos];
}

__global__ void k_hist(const void* __restrict__ ei, int E) {
    int e = blockIdx.x * blockDim.x + threadIdx.x;
    if (e < E) {
        int dst = load_idx(ei, (long long)E + e);
        atomicAdd(&g_deg[dst], 1);
    }
}

// ---------------- 3-phase coalesced scan -------------------------------------
__global__ void __launch_bounds__(SCAN_T) k_blocksum(int n) {
    int i = blockIdx.x * SCAN_T + threadIdx.x;
    int v = (i < n) ? g_deg[i] : 0;
    int lane = threadIdx.x & 31, wid = threadIdx.x >> 5;
#pragma unroll
    for (int off = 16; off > 0; off >>= 1)
        v += __shfl_down_sync(0xffffffffu, v, off);
    __shared__ int ws[32];
    if (lane == 0) ws[wid] = v;
    __syncthreads();
    if (wid == 0) {
        int s = (lane < SCAN_T / 32) ? ws[lane] : 0;
#pragma unroll
        for (int off = 16; off > 0; off >>= 1)
            s += __shfl_down_sync(0xffffffffu, s, off);
        if (lane == 0) g_bsum[blockIdx.x] = s;
    }
}

__global__ void k_scanb(int nb) {
    int lane = threadIdx.x;
    __shared__ int s[BMAX];
    s[lane] = (lane < nb) ? g_bsum[lane] : 0;
    __syncthreads();
    if (lane == 0) {
        int run = 0;
        for (int j = 0; j < nb; ++j) { int d = s[j]; s[j] = run; run += d; }
    }
    __syncthreads();
    g_bsum[lane] = s[lane];
}

__global__ void __launch_bounds__(SCAN_T) k_write(int n) {
    int i = blockIdx.x * SCAN_T + threadIdx.x;
    int d = (i < n) ? g_deg[i] : 0;
    int lane = threadIdx.x & 31, wid = threadIdx.x >> 5;

    int v = d;
#pragma unroll
    for (int off = 1; off < 32; off <<= 1) {
        int t = __shfl_up_sync(0xffffffffu, v, off);
        if (lane >= off) v += t;
    }
    __shared__ int ws[32];
    if (lane == 31) ws[wid] = v;
    __syncthreads();
    if (wid == 0) {
        int wv = ws[lane];
#pragma unroll
        for (int off = 1; off < 32; off <<= 1) {
            int t = __shfl_up_sync(0xffffffffu, wv, off);
            if (lane >= off) wv += t;
        }
        ws[lane] = wv;
    }
    __syncthreads();

    int excl = v - d + (wid ? ws[wid - 1] : 0) + g_bsum[blockIdx.x];
    if (i < n) {
        g_rowptr[i] = excl;
        g_cursor[i] = excl;
        g_dinv[i]   = rsqrtf((float)d + 1.0f);
        if (i == n - 1) g_rowptr[n] = excl + d;
    }
}

__global__ void k_scatter(const void* __restrict__ ei, int E) {
    int e = blockIdx.x * blockDim.x + threadIdx.x;
    if (e < E) {
        int src = load_idx(ei, e);
        int dst = load_idx(ei, (long long)E + e);
        int pos = atomicAdd(&g_cursor[dst], 1);
        g_csr[pos] = make_int2(src, __float_as_int(g_dinv[src]));
    }
}

// ------------- fp16 helpers --------------------------------------------------
__device__ __forceinline__ void fma_h4(uint2 p, float w, float4& a) {
    float2 lo = __half22float2(*(const __half2*)&p.x);
    float2 hi = __half22float2(*(const __half2*)&p.y);
    a.x = fmaf(w, lo.x, a.x); a.y = fmaf(w, lo.y, a.y);
    a.z = fmaf(w, hi.x, a.z); a.w = fmaf(w, hi.y, a.w);
}
__device__ __forceinline__ uint2 pack_h4(float4 r) {
    __half2 lo = __floats2half2_rn(r.x, r.y);
    __half2 hi = __floats2half2_rn(r.z, r.w);
    uint2 p;
    p.x = *(const unsigned int*)&lo;
    p.y = *(const unsigned int*)&hi;
    return p;
}
__device__ __forceinline__ unsigned int smem_u32(const void* p) {
    return (unsigned int)__cvta_generic_to_shared(p);
}

// ---------------- HMMA GEMM (known good) -------------------------------------
__global__ void __launch_bounds__(256) k_gemm_mma(
    const float* __restrict__ x, const float* __restrict__ b,
    float* __restrict__ out, int n)
{
    __shared__ __align__(16) __half sA[BM][D + 8];
    __shared__ __align__(16) __half sW[D][D + 8];

    int tid  = threadIdx.x;
    int warp = tid >> 5;
    int lane = tid & 31;
    int rowb = blockIdx.x * BM;
    int rows = n - rowb; if (rows > BM) rows = BM;

    const uint4* Wh4 = (const uint4*)g_Wh;
#pragma unroll
    for (int i = tid; i < D * (D / 8); i += 256) {
        int r = i >> 4, c = i & 15;
        *(uint4*)&sW[r][c * 8] = __ldg(&Wh4[r * 16 + c]);
    }
    const float4* x4 = (const float4*)(x + (long long)rowb * D);
    for (int i = tid; i < rows * D4; i += 256) {
        int r = i >> 5, c = i & 31;
        float4 v = x4[i];
        *(half2*)&sA[r][c * 4]     = __floats2half2_rn(v.x, v.y);
        *(half2*)&sA[r][c * 4 + 2] = __floats2half2_rn(v.z, v.w);
    }
    __syncthreads();

    int rg = warp & 1, cg = warp >> 1;
    int r0 = rg * 16;

    float acc[4][4];
#pragma unroll
    for (int j = 0; j < 4; ++j)
#pragma unroll
        for (int q = 0; q < 4; ++q) acc[j][q] = 0.f;

    int aRow = r0 + (lane & 15);
    int aCol = (lane >> 4) << 3;
    int bN = (lane & 7) + ((lane >> 4) << 3);
    int bK = ((lane >> 3) & 1) << 3;

#pragma unroll
    for (int k0 = 0; k0 < D; k0 += 16) {
        unsigned int a0, a1, a2, a3;
        unsigned int aAddr = smem_u32(&sA[aRow][k0 + aCol]);
        asm volatile("ldmatrix.sync.aligned.m8n8.x4.shared.b16 {%0,%1,%2,%3}, [%4];"
                     : "=r"(a0), "=r"(a1), "=r"(a2), "=r"(a3) : "r"(aAddr));
#pragma unroll
        for (int h16 = 0; h16 < 2; ++h16) {
            int nbase = cg * 32 + h16 * 16;
            unsigned int b0, b1, b2, b3;
            unsigned int bAddr = smem_u32(&sW[nbase + bN][k0 + bK]);
            asm volatile("ldmatrix.sync.aligned.m8n8.x4.shared.b16 {%0,%1,%2,%3}, [%4];"
                         : "=r"(b0), "=r"(b1), "=r"(b2), "=r"(b3) : "r"(bAddr));
            int j0 = h16 * 2;
            asm volatile("mma.sync.aligned.m16n8k16.row.col.f32.f16.f16.f32 "
                         "{%0,%1,%2,%3},{%4,%5,%6,%7},{%8,%9},{%0,%1,%2,%3};"
                         : "+f"(acc[j0][0]), "+f"(acc[j0][1]), "+f"(acc[j0][2]), "+f"(acc[j0][3])
                         : "r"(a0), "r"(a1), "r"(a2), "r"(a3), "r"(b0), "r"(b1));
            asm volatile("mma.sync.aligned.m16n8k16.row.col.f32.f16.f16.f32 "
                         "{%0,%1,%2,%3},{%4,%5,%6,%7},{%8,%9},{%0,%1,%2,%3};"
                         : "+f"(acc[j0+1][0]), "+f"(acc[j0+1][1]), "+f"(acc[j0+1][2]), "+f"(acc[j0+1][3])
                         : "r"(a0), "r"(a1), "r"(a2), "r"(a3), "r"(b2), "r"(b3));
        }
    }

    float c0 = g_coeff[0];
    int mlo = rowb + r0 + (lane >> 2);
    int mhi = mlo + 8;
    __half2* h0 = (__half2*)g_bufA;

#pragma unroll
    for (int j = 0; j < 4; ++j) {
        int col = cg * 32 + j * 8 + ((lane & 3) << 1);
        float2 bb = __ldg((const float2*)(b + col));
        if (mlo < n) {
            long long idx = (long long)mlo * D + col;
            *(float2*)(out + idx) = make_float2(fmaf(c0, acc[j][0], bb.x),
                                                fmaf(c0, acc[j][1], bb.y));
            h0[idx >> 1] = __floats2half2_rn(acc[j][0], acc[j][1]);
        }
        if (mhi < n) {
            long long idx = (long long)mhi * D + col;
            *(float2*)(out + idx) = make_float2(fmaf(c0, acc[j][2], bb.x),
                                                fmaf(c0, acc[j][3], bb.y));
            h0[idx >> 1] = __floats2half2_rn(acc[j][2], acc[j][3]);
        }
    }
}

// ---------------- one diffusion hop (R8 body, 128-thread blocks) -------------
__global__ void __launch_bounds__(128) k_hop(
    int flip, int k, int n, float4* __restrict__ out, int do_out, int write_h)
{
    int gw = (blockIdx.x * blockDim.x + threadIdx.x) >> 5;
    if (gw >= n) return;
    int lane = threadIdx.x & 31;

    const uint2* __restrict__ hin  = flip ? (const uint2*)g_bufB : (const uint2*)g_bufA;
    uint2*       __restrict__ hout = flip ? (uint2*)g_bufA       : (uint2*)g_bufB;

    int beg = g_rowptr[gw];
    int end = g_rowptr[gw + 1];

    uint2 ps = __ldg(&hin[gw * DH2 + lane]);

    float4 acc  = make_float4(0.f,0.f,0.f,0.f);
    float4 acc2 = make_float4(0.f,0.f,0.f,0.f);

    int e = beg;
    for (; e + 8 <= end; e += 8) {
        int2 c0 = __ldg(&g_csr[e + 0]);
        int2 c1 = __ldg(&g_csr[e + 1]);
        int2 c2 = __ldg(&g_csr[e + 2]);
        int2 c3 = __ldg(&g_csr[e + 3]);
        int2 c4 = __ldg(&g_csr[e + 4]);
        int2 c5 = __ldg(&g_csr[e + 5]);
        int2 c6 = __ldg(&g_csr[e + 6]);
        int2 c7 = __ldg(&g_csr[e + 7]);
        uint2 p0 = __ldg(&hin[c0.x * DH2 + lane]);
        uint2 p1 = __ldg(&hin[c1.x * DH2 + lane]);
        uint2 p2 = __ldg(&hin[c2.x * DH2 + lane]);
        uint2 p3 = __ldg(&hin[c3.x * DH2 + lane]);
        uint2 p4 = __ldg(&hin[c4.x * DH2 + lane]);
        uint2 p5 = __ldg(&hin[c5.x * DH2 + lane]);
        uint2 p6 = __ldg(&hin[c6.x * DH2 + lane]);
        uint2 p7 = __ldg(&hin[c7.x * DH2 + lane]);
        fma_h4(p0, __int_as_float(c0.y), acc);
        fma_h4(p1, __int_as_float(c1.y), acc2);
        fma_h4(p2, __int_as_float(c2.y), acc);
        fma_h4(p3, __int_as_float(c3.y), acc2);
        fma_h4(p4, __int_as_float(c4.y), acc);
        fma_h4(p5, __int_as_float(c5.y), acc2);
        fma_h4(p6, __int_as_float(c6.y), acc);
        fma_h4(p7, __int_as_float(c7.y), acc2);
    }
    for (; e + 4 <= end; e += 4) {
        int2 c0 = __ldg(&g_csr[e + 0]);
        int2 c1 = __ldg(&g_csr[e + 1]);
        int2 c2 = __ldg(&g_csr[e + 2]);
        int2 c3 = __ldg(&g_csr[e + 3]);
        uint2 p0 = __ldg(&hin[c0.x * DH2 + lane]);
        uint2 p1 = __ldg(&hin[c1.x * DH2 + lane]);
        uint2 p2 = __ldg(&hin[c2.x * DH2 + lane]);
        uint2 p3 = __ldg(&hin[c3.x * DH2 + lane]);
        fma_h4(p0, __int_as_float(c0.y), acc);
        fma_h4(p1, __int_as_float(c1.y), acc2);
        fma_h4(p2, __int_as_float(c2.y), acc);
        fma_h4(p3, __int_as_float(c3.y), acc2);
    }
    for (; e < end; ++e) {
        int2 c = __ldg(&g_csr[e]);
        uint2 p = __ldg(&hin[c.x * DH2 + lane]);
        fma_h4(p, __int_as_float(c.y), acc);
    }

    float di  = g_dinv[gw];
    float di2 = di * di;
    float2 slo = __half22float2(*(const __half2*)&ps.x);
    float2 shi = __half22float2(*(const __half2*)&ps.y);

    float4 r;
    r.x = fmaf(di, acc.x + acc2.x, di2 * slo.x);
    r.y = fmaf(di, acc.y + acc2.y, di2 * slo.y);
    r.z = fmaf(di, acc.z + acc2.z, di2 * shi.x);
    r.w = fmaf(di, acc.w + acc2.w, di2 * shi.y);

    int idx = gw * DH2 + lane;
    if (write_h) hout[idx] = pack_h4(r);

    if (do_out) {
        float cp = g_coeff[k - 1];
        float c  = g_coeff[k];
        float4 o = out[idx];
        o.x = fmaf(cp, slo.x, o.x);
        o.y = fmaf(cp, slo.y, o.y);
        o.z = fmaf(cp, shi.x, o.z);
        o.w = fmaf(cp, shi.y, o.w);
        o.x = fmaf(c, r.x, o.x);
        o.y = fmaf(c, r.y, o.y);
        o.z = fmaf(c, r.z, o.z);
        o.w = fmaf(c, r.w, o.w);
        out[idx] = o;
    }
}

// ---------------- launch ------------------------------------------------------
extern "C" void kernel_launch(void* const* d_in, const int* in_sizes, int n_in,
                              void* d_out, int out_size) {
    const float* x  = (const float*)d_in[0];
    const void*  ei = d_in[1];
    const float* t  = (const float*)d_in[2];
    const float* W  = (const float*)d_in[3];
    const float* b  = (const float*)d_in[4];
    float* out = (float*)d_out;

    int N = in_sizes[0] / D;
    int E = in_sizes[1] / 2;
    int nb = (N + SCAN_T - 1) / SCAN_T;
    int setup_elems = (N > D * D) ? N : D * D;

    k_setup<<<(setup_elems + 255) / 256, 256>>>(ei, t, W, N);
    k_hist<<<(E + 255) / 256, 256>>>(ei, E);
    k_blocksum<<<nb, SCAN_T>>>(N);
    k_scanb<<<1, BMAX>>>(nb);
    k_write<<<nb, SCAN_T>>>(N);
    k_scatter<<<(E + 255) / 256, 256>>>(ei, E);
    k_gemm_mma<<<(N + BM - 1) / BM, 256>>>(x, b, out, N);

    int hop_blocks = (N + 3) / 4;   // 4 warps per block, warp per node
    for (int k = 1; k <= KHOPS; ++k) {
        int flip    = (k - 1) & 1;
        int do_out  = (k & 1) == 0;
        int write_h = (k < KHOPS);
        k_hop<<<hop_blocks, 128>>>(flip, k, N, (float4*)out, do_out, write_h);
    }
}